// round 1
// baseline (speedup 1.0000x reference)
#include <cuda_runtime.h>
#include <cuda_bf16.h>
#include <math.h>

// ---------------- problem constants ----------------
#define BB 2
#define DIMC 256
#define GG 4
#define CHG 64          // DIM/GROUPS
#define OFFD 128
#define NBG 8           // B*GROUPS
#define FF 4
#define HH 16
#define WW 16
#define PQ 1024         // F*H*W
#define FD 2
#define HD 8
#define WD 8
#define PJ 128          // FD*HD*WD
#define NHEADS 8
#define DH 64
#define CPB 64
#define INNER 512
#define IT 8            // queries per block in kernel D

// ---------------- scratch (static device memory; no allocs allowed) -------
__device__ float g_q[NBG * OFFD * PQ];        // (bg, 128, 1024)  4 MB
__device__ float g_grid[NBG * PJ * 3];        // normalized kv coords
__device__ float g_k[NBG * OFFD * PJ];        // (bg, 128, 128)
__device__ float g_v[NBG * OFFD * PJ];
__device__ float g_att[BB * INNER * PQ];      // (b, 512, 1024)   2 MB

// ---------------- packed f32x2 helpers ----------------
__device__ __forceinline__ unsigned long long ffma2(unsigned long long a,
                                                    unsigned long long b,
                                                    unsigned long long c) {
    unsigned long long d;
    asm("fma.rn.f32x2 %0, %1, %2, %3;" : "=l"(d) : "l"(a), "l"(b), "l"(c));
    return d;
}
__device__ __forceinline__ unsigned long long pack2(float lo, float hi) {
    unsigned long long d;
    asm("mov.b64 %0, {%1, %2};" : "=l"(d) : "f"(lo), "f"(hi));
    return d;
}
__device__ __forceinline__ float2 unpack2(unsigned long long v) {
    float2 r;
    asm("mov.b64 {%0, %1}, %2;" : "=f"(r.x), "=f"(r.y) : "l"(v));
    return r;
}

// ============================================================
// Kernel A: grouped 1x1 conv -> q   (bg,128,1024)
// ============================================================
__global__ void k_qproj(const float* __restrict__ x, const float* __restrict__ wq) {
    const int bg = blockIdx.y;              // 0..7
    const int b = bg >> 2, g = bg & 3;
    const int p0 = blockIdx.x * 16;
    const int o = threadIdx.x;              // 0..127

    __shared__ float xs[CHG * 16];
    for (int e = threadIdx.x; e < CHG * 16; e += 128) {
        int i = e >> 4, p = e & 15;
        xs[e] = x[(size_t)(b * DIMC + g * CHG + i) * PQ + p0 + p];
    }
    __syncthreads();

    float wr[CHG];
#pragma unroll
    for (int i = 0; i < CHG; i++) wr[i] = wq[(g * OFFD + o) * CHG + i];

    for (int p = 0; p < 16; p++) {
        float acc = 0.f;
#pragma unroll
        for (int i = 0; i < CHG; i++) acc = fmaf(wr[i], xs[i * 16 + p], acc);
        g_q[(size_t)(bg * OFFD + o) * PQ + p0 + p] = acc;
    }
}

// ============================================================
// Kernel B: depthwise 4^3 stride-2 conv + GELU + 1x1 + tanh -> grid coords
// block = (pos, bg), 128 threads = channel
// ============================================================
__global__ void k_offsets(const float* __restrict__ dww, const float* __restrict__ dwb,
                          const float* __restrict__ pww) {
    const int pos = blockIdx.x;     // 0..127
    const int bg = blockIdx.y;
    const int c = threadIdx.x;

    const int zo = pos >> 6;
    const int yo = (pos >> 3) & 7;
    const int xo = pos & 7;

    const float* qrow = g_q + (size_t)(bg * OFFD + c) * PQ;
    float acc = 0.f;
#pragma unroll
    for (int kz = 0; kz < 4; kz++) {
        int z = 2 * zo - 1 + kz;
        if (z < 0 || z >= FF) continue;
#pragma unroll
        for (int ky = 0; ky < 4; ky++) {
            int y = 2 * yo - 1 + ky;
            if (y < 0 || y >= HH) continue;
#pragma unroll
            for (int kx = 0; kx < 4; kx++) {
                int xx = 2 * xo - 1 + kx;
                if (xx < 0 || xx >= WW) continue;
                acc = fmaf(qrow[(z * HH + y) * WW + xx],
                           dww[c * 64 + (kz * 4 + ky) * 4 + kx], acc);
            }
        }
    }
    float v = acc + dwb[c];
    float act = 0.5f * v * (1.f + erff(v * 0.70710678118654752f));

    __shared__ float acts[OFFD];
    acts[c] = act;
    __syncthreads();

    if (c == 0) {
        float s0 = 0.f, s1 = 0.f, s2 = 0.f;
        for (int cc = 0; cc < OFFD; cc++) {
            float a = acts[cc];
            s0 = fmaf(a, pww[0 * OFFD + cc], s0);
            s1 = fmaf(a, pww[1 * OFFD + cc], s1);
            s2 = fmaf(a, pww[2 * OFFD + cc], s2);
        }
        float of = tanhf(s0) * 2.0f;
        float oh = tanhf(s1) * 2.0f;
        float ow = tanhf(s2) * 2.0f;
        float vf = (float)zo + of;
        float vh = (float)yo + oh;
        float vw = (float)xo + ow;
        // norm_coords with sizes (fd,hd,wd): divisors max(size-1,1) = 1,7,7
        float gf = 2.0f * vf / 1.0f - 1.0f;
        float gh = 2.0f * vh / 7.0f - 1.0f;
        float gw = 2.0f * vw / 7.0f - 1.0f;
        float* gp = g_grid + (size_t)(bg * PJ + pos) * 3;
        gp[0] = gf; gp[1] = gh; gp[2] = gw;
    }
}

// ============================================================
// Kernel C: trilinear grid-sample + k/v projections
// block = (j, bg), 128 threads
// NOTE axis mixing (faithful to reference): grid[...,0] (f-norm) -> W axis,
//      grid[...,1] (h-norm) -> H axis, grid[...,2] (w-norm) -> D axis.
// ============================================================
__global__ void k_sample_kv(const float* __restrict__ x, const float* __restrict__ wk,
                            const float* __restrict__ wv) {
    const int j = blockIdx.x;
    const int bg = blockIdx.y;
    const int b = bg >> 2, g = bg & 3;
    const int tid = threadIdx.x;

    const float* gp = g_grid + (size_t)(bg * PJ + j) * 3;
    const float g0 = gp[0], g1 = gp[1], g2 = gp[2];

    __shared__ float kvs[CHG];

    if (tid < CHG) {
        float ix = ((g0 + 1.f) * (float)WW - 1.f) * 0.5f;
        float iy = ((g1 + 1.f) * (float)HH - 1.f) * 0.5f;
        float iz = ((g2 + 1.f) * (float)FF - 1.f) * 0.5f;
        float fx0 = floorf(ix), fy0 = floorf(iy), fz0 = floorf(iz);
        float tx = ix - fx0, ty = iy - fy0, tz = iz - fz0;
        int x0 = (int)fx0, y0 = (int)fy0, z0 = (int)fz0;

        const float* xp = x + (size_t)(b * DIMC + g * CHG + tid) * PQ;
        float acc = 0.f;
#pragma unroll
        for (int dz = 0; dz < 2; dz++)
#pragma unroll
            for (int dy = 0; dy < 2; dy++)
#pragma unroll
                for (int dx = 0; dx < 2; dx++) {
                    int xc = x0 + dx, yc = y0 + dy, zc = z0 + dz;
                    float wgt = (dx ? tx : 1.f - tx) * (dy ? ty : 1.f - ty) *
                                (dz ? tz : 1.f - tz);
                    bool valid = (xc >= 0) & (xc < WW) & (yc >= 0) & (yc < HH) &
                                 (zc >= 0) & (zc < FF);
                    int xi = min(max(xc, 0), WW - 1);
                    int yi = min(max(yc, 0), HH - 1);
                    int zi = min(max(zc, 0), FF - 1);
                    float val = xp[(zi * HH + yi) * WW + xi];
                    acc += valid ? val * wgt : 0.f;
                }
        kvs[tid] = acc;
    }
    __syncthreads();

    // tid = output channel o (0..127)
    float ak = 0.f, av = 0.f;
#pragma unroll
    for (int i = 0; i < CHG; i++) {
        float kv = kvs[i];
        ak = fmaf(wk[(g * OFFD + tid) * CHG + i], kv, ak);
        av = fmaf(wv[(g * OFFD + tid) * CHG + i], kv, av);
    }
    g_k[(size_t)(bg * OFFD + tid) * PJ + j] = ak;
    g_v[(size_t)(bg * OFFD + tid) * PJ + j] = av;
}

// ============================================================
// Kernel D: fused sim + CPB MLP + softmax + attn@V   (dominant)
// block = (i-tile, bg); 128 threads = key index j; IT=8 queries per block
// ============================================================
__global__ __launch_bounds__(128, 4)
void k_attn(const float* __restrict__ cw0, const float* __restrict__ cb0,
            const float* __restrict__ cw1, const float* __restrict__ cb1,
            const float* __restrict__ cw2, const float* __restrict__ cb2) {
    const int bg = blockIdx.y;
    const int b = bg >> 2, g = bg & 3;
    const int i0 = blockIdx.x * IT;
    const int j = threadIdx.x;
    const int lane = j & 31, wid = j >> 5;

    __shared__ __align__(16) float w1t[CPB * CPB];   // [o][i] transposed
    __shared__ __align__(16) float qs[OFFD * IT];    // [o][ii], scaled
    __shared__ __align__(16) float attns[IT * 2 * PJ];
    __shared__ float w0s[3 * CPB], b0s[CPB], b1s[CPB];
    __shared__ float w2s0[CPB], w2s1[CPB], b2s[2];
    __shared__ float red[8];

    for (int e = j; e < CPB * CPB; e += 128) {
        int iin = e >> 6, o = e & 63;
        w1t[o * CPB + iin] = cw1[e];
    }
    for (int e = j; e < 3 * CPB; e += 128) w0s[e] = cw0[e];
    if (j < CPB) {
        b0s[j] = cb0[j];
        b1s[j] = cb1[j];
        w2s0[j] = cw2[j * 2 + 0];
        w2s1[j] = cw2[j * 2 + 1];
    }
    if (j < 2) b2s[j] = cb2[j];
    {
        const float* qp = g_q + (size_t)(bg * OFFD + j) * PQ + i0;
#pragma unroll
        for (int t = 0; t < IT; t++) qs[j * IT + t] = qp[t] * 0.125f;  // scale=1/8
    }
    const float* gp = g_grid + (size_t)(bg * PJ + j) * 3;
    const float gj0 = gp[0], gj1 = gp[1], gj2 = gp[2];
    __syncthreads();

    // ---- sim: two head halves ----
    float sim0[IT], sim1[IT];
#pragma unroll
    for (int t = 0; t < IT; t++) { sim0[t] = 0.f; sim1[t] = 0.f; }
    const float* kb = g_k + (size_t)bg * OFFD * PJ + j;
#pragma unroll 4
    for (int o = 0; o < 64; o++) {
        float kv = kb[o * PJ];
        float4 qa = *(const float4*)(qs + o * IT);
        float4 qbv = *(const float4*)(qs + o * IT + 4);
        sim0[0] = fmaf(qa.x, kv, sim0[0]); sim0[1] = fmaf(qa.y, kv, sim0[1]);
        sim0[2] = fmaf(qa.z, kv, sim0[2]); sim0[3] = fmaf(qa.w, kv, sim0[3]);
        sim0[4] = fmaf(qbv.x, kv, sim0[4]); sim0[5] = fmaf(qbv.y, kv, sim0[5]);
        sim0[6] = fmaf(qbv.z, kv, sim0[6]); sim0[7] = fmaf(qbv.w, kv, sim0[7]);
    }
#pragma unroll 4
    for (int o = 64; o < 128; o++) {
        float kv = kb[o * PJ];
        float4 qa = *(const float4*)(qs + o * IT);
        float4 qbv = *(const float4*)(qs + o * IT + 4);
        sim1[0] = fmaf(qa.x, kv, sim1[0]); sim1[1] = fmaf(qa.y, kv, sim1[1]);
        sim1[2] = fmaf(qa.z, kv, sim1[2]); sim1[3] = fmaf(qa.w, kv, sim1[3]);
        sim1[4] = fmaf(qbv.x, kv, sim1[4]); sim1[5] = fmaf(qbv.y, kv, sim1[5]);
        sim1[6] = fmaf(qbv.z, kv, sim1[6]); sim1[7] = fmaf(qbv.w, kv, sim1[7]);
    }

    // ---- per query: CPB MLP + softmax ----
    for (int t = 0; t < IT; t++) {
        const int i = i0 + t;
        const int zf = i >> 8, yq = (i >> 4) & 15, xq = i & 15;
        const float gq0 = 2.0f * (float)zf / 3.0f - 1.0f;
        const float gq1 = 2.0f * (float)yq / 15.0f - 1.0f;
        const float gq2 = 2.0f * (float)xq / 15.0f - 1.0f;
        float p0 = gq0 - gj0, p1 = gq1 - gj1, p2 = gq2 - gj2;
        float t0 = copysignf(log1pf(fabsf(p0)), p0);
        float t1 = copysignf(log1pf(fabsf(p1)), p1);
        float t2 = copysignf(log1pf(fabsf(p2)), p2);

        // layer0: 3 -> 64, packed into 32 f32x2 regs
        unsigned long long h0p[32];
#pragma unroll
        for (int q = 0; q < 32; q++) {
            float va = fmaf(t0, w0s[2 * q],
                       fmaf(t1, w0s[64 + 2 * q],
                       fmaf(t2, w0s[128 + 2 * q], b0s[2 * q])));
            float vb = fmaf(t0, w0s[2 * q + 1],
                       fmaf(t1, w0s[64 + 2 * q + 1],
                       fmaf(t2, w0s[128 + 2 * q + 1], b0s[2 * q + 1])));
            h0p[q] = pack2(fmaxf(va, 0.f), fmaxf(vb, 0.f));
        }

        // layer1 (64x64) + layer2 (64x2), f32x2 packed
        float out0 = b2s[0], out1 = b2s[1];
#pragma unroll 2
        for (int oo = 0; oo < CPB; oo++) {
            const ulonglong2* wr = (const ulonglong2*)(w1t + oo * CPB);
            unsigned long long accA = 0ull, accB = 0ull;
#pragma unroll
            for (int q = 0; q < 16; q++) {
                ulonglong2 wv = wr[q];
                accA = ffma2(wv.x, h0p[2 * q], accA);
                accB = ffma2(wv.y, h0p[2 * q + 1], accB);
            }
            float2 fa = unpack2(accA), fb = unpack2(accB);
            float hv = fmaxf(fa.x + fa.y + fb.x + fb.y + b1s[oo], 0.f);
            out0 = fmaf(hv, w2s0[oo], out0);
            out1 = fmaf(hv, w2s1[oo], out1);
        }

        float l0 = sim0[t] + out0;
        float l1 = sim1[t] + out1;

        // block softmax over 128 j (both heads)
        float m0 = l0, m1 = l1;
#pragma unroll
        for (int off = 16; off; off >>= 1) {
            m0 = fmaxf(m0, __shfl_xor_sync(0xffffffffu, m0, off));
            m1 = fmaxf(m1, __shfl_xor_sync(0xffffffffu, m1, off));
        }
        if (lane == 0) { red[wid] = m0; red[4 + wid] = m1; }
        __syncthreads();
        m0 = fmaxf(fmaxf(red[0], red[1]), fmaxf(red[2], red[3]));
        m1 = fmaxf(fmaxf(red[4], red[5]), fmaxf(red[6], red[7]));
        __syncthreads();
        float e0 = __expf(l0 - m0), e1 = __expf(l1 - m1);
        float s0 = e0, s1 = e1;
#pragma unroll
        for (int off = 16; off; off >>= 1) {
            s0 += __shfl_xor_sync(0xffffffffu, s0, off);
            s1 += __shfl_xor_sync(0xffffffffu, s1, off);
        }
        if (lane == 0) { red[wid] = s0; red[4 + wid] = s1; }
        __syncthreads();
        s0 = red[0] + red[1] + red[2] + red[3];
        s1 = red[4] + red[5] + red[6] + red[7];
        __syncthreads();
        attns[t * 2 * PJ + j] = e0 / s0;
        attns[t * 2 * PJ + PJ + j] = e1 / s1;
    }
    __syncthreads();

    // ---- attn @ V : thread = output channel o ----
    const int o = j, e = o >> 6;
    const ulonglong2* vrow = (const ulonglong2*)(g_v + (size_t)(bg * OFFD + o) * PJ);
    for (int t = 0; t < IT; t++) {
        const ulonglong2* arow = (const ulonglong2*)(attns + t * 2 * PJ + e * PJ);
        unsigned long long accA = 0ull, accB = 0ull;
#pragma unroll
        for (int q = 0; q < 32; q++) {
            ulonglong2 av = arow[q];
            ulonglong2 vv = vrow[q];
            accA = ffma2(av.x, vv.x, accA);
            accB = ffma2(av.y, vv.y, accB);
        }
        float2 fa = unpack2(accA), fb = unpack2(accB);
        g_att[(size_t)(b * INNER + g * OFFD + o) * PQ + i0 + t] =
            fa.x + fa.y + fb.x + fb.y;
    }
}

// ============================================================
// Kernel E: output projection  out[b,o,p] = sum_c wo[o,c]*att[b,c,p] + bo[o]
// tiled GEMM: BM=64 (o), BN=64 (p), BK=16
// ============================================================
__global__ void k_oproj(const float* __restrict__ wo, const float* __restrict__ bo,
                        float* __restrict__ out) {
    const int p0 = blockIdx.x * 64;
    const int o0 = blockIdx.y * 64;
    const int b = blockIdx.z;
    const int tid = threadIdx.x;        // 256
    const int tx = tid & 15, ty = tid >> 4;

    __shared__ __align__(16) float As[16 * 64];   // [k][m]
    __shared__ __align__(16) float Bs[16 * 64];   // [k][n]

    float acc[4][4];
#pragma unroll
    for (int a = 0; a < 4; a++)
#pragma unroll
        for (int c = 0; c < 4; c++) acc[a][c] = 0.f;

    for (int k0 = 0; k0 < INNER; k0 += 16) {
        {
            int m = tid >> 2, kq = (tid & 3) * 4;
            float4 wv = *(const float4*)(wo + (size_t)(o0 + m) * INNER + k0 + kq);
            As[(kq + 0) * 64 + m] = wv.x;
            As[(kq + 1) * 64 + m] = wv.y;
            As[(kq + 2) * 64 + m] = wv.z;
            As[(kq + 3) * 64 + m] = wv.w;
            int k = tid >> 4, pq = (tid & 15) * 4;
            float4 bv = *(const float4*)(g_att + (size_t)(b * INNER + k0 + k) * PQ + p0 + pq);
            *(float4*)(Bs + k * 64 + pq) = bv;
        }
        __syncthreads();
#pragma unroll
        for (int k = 0; k < 16; k++) {
            float4 am = *(const float4*)(As + k * 64 + ty * 4);
            float4 bn = *(const float4*)(Bs + k * 64 + tx * 4);
            float a4[4] = {am.x, am.y, am.z, am.w};
            float b4[4] = {bn.x, bn.y, bn.z, bn.w};
#pragma unroll
            for (int a = 0; a < 4; a++)
#pragma unroll
                for (int c = 0; c < 4; c++) acc[a][c] = fmaf(a4[a], b4[c], acc[a][c]);
        }
        __syncthreads();
    }
#pragma unroll
    for (int a = 0; a < 4; a++) {
        float bias = bo[o0 + ty * 4 + a];
#pragma unroll
        for (int c = 0; c < 4; c++)
            out[(size_t)(b * DIMC + o0 + ty * 4 + a) * PQ + p0 + tx * 4 + c] =
                acc[a][c] + bias;
    }
}

// ============================================================
extern "C" void kernel_launch(void* const* d_in, const int* in_sizes, int n_in,
                              void* d_out, int out_size) {
    const float* x    = (const float*)d_in[0];
    const float* wq   = (const float*)d_in[1];
    const float* wk   = (const float*)d_in[2];
    const float* wv   = (const float*)d_in[3];
    const float* dww  = (const float*)d_in[4];
    const float* dwb  = (const float*)d_in[5];
    const float* pww  = (const float*)d_in[6];
    const float* cw0  = (const float*)d_in[7];
    const float* cb0  = (const float*)d_in[8];
    const float* cw1  = (const float*)d_in[9];
    const float* cb1  = (const float*)d_in[10];
    const float* cw2  = (const float*)d_in[11];
    const float* cb2  = (const float*)d_in[12];
    const float* wo   = (const float*)d_in[13];
    const float* bo   = (const float*)d_in[14];
    float* out = (float*)d_out;

    k_qproj<<<dim3(PQ / 16, NBG), 128>>>(x, wq);
    k_offsets<<<dim3(PJ, NBG), 128>>>(dww, dwb, pww);
    k_sample_kv<<<dim3(PJ, NBG), 128>>>(x, wk, wv);
    k_attn<<<dim3(PQ / IT, NBG), 128>>>(cw0, cb0, cw1, cb1, cw2, cb2);
    k_oproj<<<dim3(PQ / 64, DIMC / 64, BB), 256>>>(wo, bo, out);
}